// round 15
// baseline (speedup 1.0000x reference)
#include <cuda_runtime.h>
#include <cuda_bf16.h>
#include <math.h>
#include <float.h>
#include <stdint.h>

// B=4, Sq=Skv=1024, H=16, Dh=64. d_out: [out 4M][attn 4M] fp32.
// Tensor work via baseline-PTX mma.sync (HMMA): tcgen05 unavailable (harness
// compiles through virtual arch compute_103, no 'a' suffix).

__device__ __nv_bfloat16 g_inhi[8u << 20], g_inlo[8u << 20];  // q(scaled)|k
__device__ __nv_bfloat16 g_whi[2u << 20],  g_wlo[2u << 20];   // Wq|Wk
__device__ __nv_bfloat16 g_pphi[8u << 20], g_pplo[8u << 20];  // qp|kp hi/lo
__device__ float         g_part[8u << 20];                     // attn partials (2 halves)
__device__ __nv_bfloat16 g_athi[4u << 20], g_atlo[4u << 20];  // attn hi/lo
__device__ __nv_bfloat16 g_vthi[4u << 20], g_vtlo[4u << 20];  // v^T hi/lo

// ---------------- helpers ----------------------------------------------------
__device__ __forceinline__ uint32_t smem_u32(const void* p) {
    uint32_t a;
    asm("{ .reg .u64 t; cvta.to.shared.u64 t, %1; cvt.u32.u64 %0, t; }" : "=r"(a) : "l"(p));
    return a;
}
__device__ __forceinline__ void mma16816(float* c, const uint32_t* a, const uint32_t* b) {
    asm volatile(
        "mma.sync.aligned.m16n8k16.row.col.f32.bf16.bf16.f32 "
        "{%0,%1,%2,%3}, {%4,%5,%6,%7}, {%8,%9}, {%0,%1,%2,%3};"
        : "+f"(c[0]), "+f"(c[1]), "+f"(c[2]), "+f"(c[3])
        : "r"(a[0]), "r"(a[1]), "r"(a[2]), "r"(a[3]), "r"(b[0]), "r"(b[1]));
}
__device__ __forceinline__ void ldmA(uint32_t* r, uint32_t base, int row0, int kb, int lane) {
    int sub = lane >> 3, rr = lane & 7;
    int row = row0 + rr + ((sub & 1) << 3);
    int ch  = kb + (sub >> 1);
    uint32_t addr = base + row * 128 + ((ch ^ (row & 7)) << 4);
    asm volatile("ldmatrix.sync.aligned.m8n8.x4.shared.b16 {%0,%1,%2,%3}, [%4];"
                 : "=r"(r[0]), "=r"(r[1]), "=r"(r[2]), "=r"(r[3]) : "r"(addr));
}
__device__ __forceinline__ void ldmB(uint32_t* r, uint32_t base, int row0, int kb, int lane) {
    int sub = lane >> 3, rr = lane & 7;
    int row = row0 + rr + ((sub >> 1) << 3);
    int ch  = kb + (sub & 1);
    uint32_t addr = base + row * 128 + ((ch ^ (row & 7)) << 4);
    asm volatile("ldmatrix.sync.aligned.m8n8.x4.shared.b16 {%0,%1,%2,%3}, [%4];"
                 : "=r"(r[0]), "=r"(r[1]), "=r"(r[2]), "=r"(r[3]) : "r"(addr));
}
// predicated float accumulation (all p >= 0, so float order == bit order)
__device__ __forceinline__ void padd_lt(float& s, float v, float c) {
    asm("{ .reg .pred q; setp.lt.f32 q, %1, %2; @q add.f32 %0, %0, %1; }"
        : "+f"(s) : "f"(v), "f"(c));
}
__device__ __forceinline__ void pfma_ge(float& a, float v, float inv, float c) {
    asm("{ .reg .pred q; setp.ge.f32 q, %1, %3; @q fma.rn.f32 %0, %1, %2, %0; }"
        : "+f"(a) : "f"(v), "f"(inv), "f"(c));
}
#define CP_ASYNC16(dst, src) \
    asm volatile("cp.async.cg.shared.global [%0], [%1], 16;" :: "r"(dst), "l"(src))
#define CP_COMMIT() asm volatile("cp.async.commit_group;" ::: "memory")
#define CP_WAIT0()  asm volatile("cp.async.wait_group 0;" ::: "memory")
#define CP_WAIT1()  asm volatile("cp.async.wait_group 1;" ::: "memory")
#define BARG(id)    asm volatile("bar.sync %0, 256;" :: "r"(id) : "memory")

// ---------------- split fp32 -> bf16 hi/lo, all four sources in one launch ---
__global__ void split4_kernel(const float* __restrict__ q, const float* __restrict__ k,
                              const float* __restrict__ Wq, const float* __restrict__ Wk,
                              __nv_bfloat16* __restrict__ inhi, __nv_bfloat16* __restrict__ inlo,
                              __nv_bfloat16* __restrict__ whi,  __nv_bfloat16* __restrict__ wlo) {
    const int y = blockIdx.y;
    int i = (blockIdx.x * 256 + threadIdx.x) * 4;
    const float* in;
    __nv_bfloat16 *hi, *lo;
    size_t off;
    float scale = 1.0f;
    if (y == 0)      { in = q;  hi = inhi; lo = inlo; off = 0;        scale = 0.125f; }
    else if (y == 1) { in = k;  hi = inhi; lo = inlo; off = 4u << 20; }
    else if (y == 2) { if (i >= (1 << 20)) return; in = Wq; hi = whi; lo = wlo; off = 0; }
    else             { if (i >= (1 << 20)) return; in = Wk; hi = whi; lo = wlo; off = 1u << 20; }
    float4 v = *(const float4*)(in + i);
    v.x *= scale; v.y *= scale; v.z *= scale; v.w *= scale;
    __nv_bfloat162 H0, H1, L0, L1;
    H0.x = __float2bfloat16(v.x); H0.y = __float2bfloat16(v.y);
    H1.x = __float2bfloat16(v.z); H1.y = __float2bfloat16(v.w);
    L0.x = __float2bfloat16(v.x - __bfloat162float(H0.x));
    L0.y = __float2bfloat16(v.y - __bfloat162float(H0.y));
    L1.x = __float2bfloat16(v.z - __bfloat162float(H1.x));
    L1.y = __float2bfloat16(v.w - __bfloat162float(H1.y));
    *(__nv_bfloat162*)(hi + off + i)     = H0;
    *(__nv_bfloat162*)(hi + off + i + 2) = H1;
    *(__nv_bfloat162*)(lo + off + i)     = L0;
    *(__nv_bfloat162*)(lo + off + i + 2) = L1;
}

// ---------------- v[b][k][n] -> vT hi/lo [b][n][k] ---------------------------
__global__ __launch_bounds__(256)
void transpose_split_v(const float* __restrict__ v, __nv_bfloat16* __restrict__ thi,
                       __nv_bfloat16* __restrict__ tlo) {
    __shared__ float tile[32][33];
    const int b = blockIdx.z, n0 = blockIdx.x * 32, k0 = blockIdx.y * 32;
    const int tx = threadIdx.x & 31, ty = threadIdx.x >> 5;
    const float* I = v + ((size_t)b << 20);
#pragma unroll
    for (int i = 0; i < 4; ++i)
        tile[ty + i * 8][tx] = I[(size_t)(k0 + ty + i * 8) * 1024 + n0 + tx];
    __syncthreads();
#pragma unroll
    for (int i = 0; i < 4; ++i) {
        float x = tile[tx][ty + i * 8];
        size_t o = ((size_t)b << 20) + (size_t)(n0 + ty + i * 8) * 1024 + k0 + tx;
        __nv_bfloat16 h = __float2bfloat16(x);
        thi[o] = h;
        tlo[o] = __float2bfloat16(x - __bfloat162float(h));
    }
}

// ---------------- split-bf16 NT GEMM via mma.sync ----------------------------
// Single 64KB stage buffer + __launch_bounds__(256,2) -> 2 CTAs/SM: cross-CTA
// overlap hides the per-stage load latency.
#define GEMM_SMEM 65536
template <int BF16OUT>
__global__ __launch_bounds__(256, 2)
void mma_gemm(const __nv_bfloat16* __restrict__ Ahi, const __nv_bfloat16* __restrict__ Alo,
              const __nv_bfloat16* __restrict__ Bhi, const __nv_bfloat16* __restrict__ Blo,
              float* __restrict__ Cf, __nv_bfloat16* __restrict__ Chi,
              __nv_bfloat16* __restrict__ Clo,
              size_t aMulZ, size_t bMulZ, size_t cMulZ, int K) {
    extern __shared__ char smem[];
    const uint32_t sb = smem_u32(smem);
    const int tid = threadIdx.x, wid = tid >> 5, lane = tid & 31;
    const int m0 = blockIdx.y * 128, n0 = blockIdx.x * 128, z = blockIdx.z;
    const int wm = wid >> 2, wn = wid & 3;

    const __nv_bfloat16* srcs[4] = {
        Ahi + (size_t)z * aMulZ + (size_t)m0 * 1024, Alo + (size_t)z * aMulZ + (size_t)m0 * 1024,
        Bhi + (size_t)z * bMulZ + (size_t)n0 * 1024, Blo + (size_t)z * bMulZ + (size_t)n0 * 1024 };
    const size_t coff = (size_t)z * cMulZ;

    float acc[4][4][4];
#pragma unroll
    for (int i = 0; i < 4; ++i)
#pragma unroll
        for (int j = 0; j < 4; ++j)
#pragma unroll
            for (int e = 0; e < 4; ++e) acc[i][j][e] = 0.f;

    const int lrow = tid >> 3, lc = tid & 7;
    const int nstage = K >> 6;

    {   // prefetch stage 0
#pragma unroll
        for (int mat = 0; mat < 4; ++mat) {
            const __nv_bfloat16* sp = srcs[mat] + lc * 8;
#pragma unroll
            for (int i = 0; i < 4; ++i) {
                int row = lrow + i * 32;
                uint32_t dst = sb + mat * 16384 + row * 128 + ((lc ^ (row & 7)) << 4);
                CP_ASYNC16(dst, sp + (size_t)row * 1024);
            }
        }
        CP_COMMIT();
    }

    for (int s = 0; s < nstage; ++s) {
        CP_WAIT0();
        __syncthreads();
#pragma unroll
        for (int ks = 0; ks < 4; ++ks) {
            const int kb = ks * 2;
            uint32_t ah[4][4], al[4][4];
#pragma unroll
            for (int fm = 0; fm < 4; ++fm) {
                ldmA(ah[fm], sb,         wm * 64 + fm * 16, kb, lane);
                ldmA(al[fm], sb + 16384, wm * 64 + fm * 16, kb, lane);
            }
#pragma unroll
            for (int nh = 0; nh < 2; ++nh) {
                uint32_t bh[4], bl[4];
                ldmB(bh, sb + 32768, wn * 32 + nh * 16, kb, lane);
                ldmB(bl, sb + 49152, wn * 32 + nh * 16, kb, lane);
#pragma unroll
                for (int fm = 0; fm < 4; ++fm) {
                    mma16816(acc[fm][2 * nh],     ah[fm], bh);
                    mma16816(acc[fm][2 * nh],     al[fm], bh);
                    mma16816(acc[fm][2 * nh],     ah[fm], bl);
                    mma16816(acc[fm][2 * nh + 1], ah[fm], bh + 2);
                    mma16816(acc[fm][2 * nh + 1], al[fm], bh + 2);
                    mma16816(acc[fm][2 * nh + 1], ah[fm], bl + 2);
                }
            }
        }
        __syncthreads();
        if (s + 1 < nstage) {
            const int k1 = (s + 1) << 6;
#pragma unroll
            for (int mat = 0; mat < 4; ++mat) {
                const __nv_bfloat16* sp = srcs[mat] + k1 + lc * 8;
#pragma unroll
                for (int i = 0; i < 4; ++i) {
                    int row = lrow + i * 32;
                    uint32_t dst = sb + mat * 16384 + row * 128 + ((lc ^ (row & 7)) << 4);
                    CP_ASYNC16(dst, sp + (size_t)row * 1024);
                }
            }
            CP_COMMIT();
        }
    }

    const int g = lane >> 2, tig = lane & 3;
#pragma unroll
    for (int fm = 0; fm < 4; ++fm)
#pragma unroll
        for (int j = 0; j < 4; ++j) {
            int row = m0 + wm * 64 + fm * 16 + g;
            int col = n0 + wn * 32 + j * 8 + 2 * tig;
            float d0 = acc[fm][j][0], d1 = acc[fm][j][1];
            float d2 = acc[fm][j][2], d3 = acc[fm][j][3];
            if (BF16OUT) {
                __nv_bfloat162 h0, l0, h1, l1;
                h0.x = __float2bfloat16(d0); h0.y = __float2bfloat16(d1);
                l0.x = __float2bfloat16(d0 - __bfloat162float(h0.x));
                l0.y = __float2bfloat16(d1 - __bfloat162float(h0.y));
                h1.x = __float2bfloat16(d2); h1.y = __float2bfloat16(d3);
                l1.x = __float2bfloat16(d2 - __bfloat162float(h1.x));
                l1.y = __float2bfloat16(d3 - __bfloat162float(h1.y));
                *(__nv_bfloat162*)(Chi + coff + (size_t)row * 1024 + col)       = h0;
                *(__nv_bfloat162*)(Clo + coff + (size_t)row * 1024 + col)       = l0;
                *(__nv_bfloat162*)(Chi + coff + (size_t)(row + 8) * 1024 + col) = h1;
                *(__nv_bfloat162*)(Clo + coff + (size_t)(row + 8) * 1024 + col) = l1;
            } else {
                *(float2*)(Cf + coff + (size_t)row * 1024 + col)       = make_float2(d0, d1);
                *(float2*)(Cf + coff + (size_t)(row + 8) * 1024 + col) = make_float2(d2, d3);
            }
        }
}

// ---------------- fused scores-MMA + thresholded softmax (head-split) -------
// Grid (64, 4, 2): CTA = (b, 16 q-rows, half-of-heads). Each CTA processes 8
// heads, accumulating PARTIAL head sums to g_part[z] (fp32). combine_kernel
// sums halves and emits attn fp32 + bf16 hi/lo. 512 half-length CTAs improve
// wave quantization (256 CTAs / 148 SMs = 1.73 waves -> makespan 2 waves).
// Mask is applied WRITER-side at the MMA scatter (off the select critical path).
#define SCW 1036
#define F_QP 0                       // 2 groups x 4KB
#define F_KP 8192                    // 2 groups x 2 bufs x 32KB
#define F_SC (8192 + 131072)
#define F_KM (F_SC + 16 * SCW * 4)
#define FUSED_SMEM (F_KM + 1024)

__global__ __launch_bounds__(512, 1)
void attn_fused(const __nv_bfloat16* __restrict__ qphi, const __nv_bfloat16* __restrict__ qplo,
                const __nv_bfloat16* __restrict__ kphi, const __nv_bfloat16* __restrict__ kplo,
                const int* __restrict__ kmask, float* __restrict__ part) {
    extern __shared__ char smem[];
    const uint32_t sb = smem_u32(smem);
    const int b = blockIdx.y, r0 = blockIdx.x * 16, h0 = blockIdx.z * 8;
    const int tid = threadIdx.x, warp = tid >> 5, lane = tid & 31;
    const int g = warp >> 3, gw = warp & 7, gtid = tid & 255;
    float* sc = (float*)(smem + F_SC);
    unsigned char* km = (unsigned char*)(smem + F_KM);

    const uint32_t myqp = sb + F_QP + g * 4096;
    const uint32_t kp0  = sb + F_KP + g * 65536;          // buffer 0
    const uint32_t kp1  = kp0 + 32768;                    // buffer 1

    for (int i = tid; i < 1024; i += 512)
        km[i] = (kmask[b * 1024 + i] > 0) ? 1 : 0;

    float acc[32];
#pragma unroll
    for (int t2 = 0; t2 < 32; ++t2) acc[t2] = 0.f;

    const int qmat = gtid >> 7, qrow = (gtid >> 3) & 15, qlc = gtid & 7;
    const int lrow = gtid >> 3, lc = gtid & 7;

    auto stage_qp = [&](int h) {
        const __nv_bfloat16* qsrc = (qmat ? qplo : qphi)
            + (size_t)(b * 1024 + r0 + qrow) * 1024 + h * 64 + qlc * 8;
        CP_ASYNC16(myqp + qmat * 2048 + qrow * 128 + ((qlc ^ (qrow & 7)) << 4), qsrc);
    };
    auto stage_chunk = [&](int h, int c, uint32_t buf) {
#pragma unroll
        for (int mat = 0; mat < 2; ++mat) {
            const __nv_bfloat16* base = mat ? kplo : kphi;
#pragma unroll
            for (int i = 0; i < 4; ++i) {
                int row = lrow + i * 32;
                const __nv_bfloat16* src = base
                    + (size_t)(b * 1024 + c * 128 + row) * 1024 + h * 64 + lc * 8;
                CP_ASYNC16(buf + mat * 16384 + row * 128 + ((lc ^ (row & 7)) << 4), src);
            }
        }
    };

    stage_qp(h0);
    stage_chunk(h0, g, kp0);
    CP_COMMIT();
    __syncthreads();               // km visible to both groups before scatter

    for (int hh = 0; hh < 8; ++hh) {
        const int h = h0 + hh;
        uint32_t ah[4][4], al[4][4];
        for (int ci = 0; ci < 4; ++ci) {
            const int c = g + 2 * ci;                   // this group's chunk
            const uint32_t nbuf = ((ci + 1) & 1) ? kp1 : kp0;
            if (ci < 3) {
                stage_chunk(h, c + 2, nbuf);
                CP_COMMIT();
            } else if (hh < 7) {
                stage_qp(h + 1);
                stage_chunk(h + 1, g, nbuf);
                CP_COMMIT();
            }
            if (hh == 7 && ci == 3) CP_WAIT0(); else CP_WAIT1();
            BARG(g + 1);                                // chunk c resident for group
            if (ci == 0) {
#pragma unroll
                for (int ks = 0; ks < 4; ++ks) {
                    ldmA(ah[ks], myqp,        0, 2 * ks, lane);
                    ldmA(al[ks], myqp + 2048, 0, 2 * ks, lane);
                }
            }
            const uint32_t cbuf = (ci & 1) ? kp1 : kp0;
            float c0a[4] = {0.f,0.f,0.f,0.f}, c0b[4] = {0.f,0.f,0.f,0.f};
            float c1a[4] = {0.f,0.f,0.f,0.f}, c1b[4] = {0.f,0.f,0.f,0.f};
#pragma unroll
            for (int ks = 0; ks < 4; ++ks) {
                uint32_t bh[4], bl[4];
                ldmB(bh, cbuf,         gw * 16, 2 * ks, lane);
                ldmB(bl, cbuf + 16384, gw * 16, 2 * ks, lane);
                mma16816(c0a, ah[ks], bh);
                mma16816(c0b, al[ks], bh);
                mma16816(c0b, ah[ks], bl);
                mma16816(c1a, ah[ks], bh + 2);
                mma16816(c1b, al[ks], bh + 2);
                mma16816(c1b, ah[ks], bl + 2);
            }
            {   // scatter this chunk's 16x16 score tile, mask applied here
                int gr = lane >> 2, tig = lane & 3;
                int colb = c * 128 + gw * 16 + 2 * tig;
                float k0f = km[colb]     ? 0.f : -FLT_MAX;
                float k1f = km[colb + 1] ? 0.f : -FLT_MAX;
                float k8f = km[colb + 8] ? 0.f : -FLT_MAX;
                float k9f = km[colb + 9] ? 0.f : -FLT_MAX;
                // masked value: v + 0 or -FLT_MAX (score magnitudes << FLT_MAX/2)
                *(float2*)&sc[gr * SCW + colb] =
                    make_float2(k0f + (c0a[0]+c0b[0]), k1f + (c0a[1]+c0b[1]));
                *(float2*)&sc[(gr + 8) * SCW + colb] =
                    make_float2(k0f + (c0a[2]+c0b[2]), k1f + (c0a[3]+c0b[3]));
                *(float2*)&sc[gr * SCW + colb + 8] =
                    make_float2(k8f + (c1a[0]+c1b[0]), k9f + (c1a[1]+c1b[1]));
                *(float2*)&sc[(gr + 8) * SCW + colb + 8] =
                    make_float2(k8f + (c1a[2]+c1b[2]), k9f + (c1a[3]+c1b[3]));
            }
            BARG(g + 1);                                // group done reading cbuf
        }
        __syncthreads();                                // sc complete from both groups

        // ---- select: one row per warp (row = warp); sc already masked
        {
            const int row = warp;
            float p[32];
            float m = -FLT_MAX;
#pragma unroll
            for (int c = 0; c < 8; ++c) {
                int j = c * 128 + lane * 4;
                float4 v = *(const float4*)&sc[row * SCW + j];
                p[c*4+0] = v.x; p[c*4+1] = v.y; p[c*4+2] = v.z; p[c*4+3] = v.w;
                m = fmaxf(m, fmaxf(fmaxf(v.x, v.y), fmaxf(v.z, v.w)));
            }
#pragma unroll
            for (int o = 16; o > 0; o >>= 1)
                m = fmaxf(m, __shfl_xor_sync(0xffffffffu, m, o));

            float z0 = 0.f, z1 = 0.f, z2 = 0.f, z3 = 0.f;
#pragma unroll
            for (int t2 = 0; t2 < 32; t2 += 4) {
                p[t2+0] = __expf(p[t2+0] - m); z0 += p[t2+0];
                p[t2+1] = __expf(p[t2+1] - m); z1 += p[t2+1];
                p[t2+2] = __expf(p[t2+2] - m); z2 += p[t2+2];
                p[t2+3] = __expf(p[t2+3] - m); z3 += p[t2+3];
            }
            float Z = (z0 + z1) + (z2 + z3);
#pragma unroll
            for (int o = 16; o > 0; o >>= 1)
                Z += __shfl_xor_sync(0xffffffffu, Z, o);

            const float T = 0.1f * Z;
            // 1-bit weighted radix-select, 17 rounds (bits 26..10), cutoff
            // window 1024 ulp (1.2e-4 rel). Base 0x38000000 provably below
            // cutoff (G(2^-14) < 0.1 <= T). G tracks sum(p < P) exactly, so
            // kept mass K = Z - G (no extra sweep).
            unsigned P = 0x38000000u;
            float G = 0.f;
            for (int bit = 26; bit >= 10; --bit) {
                float candf = __uint_as_float(P + (1u << bit));
                float s0 = 0.f, s1 = 0.f, s2 = 0.f, s3 = 0.f;
#pragma unroll
                for (int t2 = 0; t2 < 32; t2 += 4) {
                    padd_lt(s0, p[t2+0], candf);
                    padd_lt(s1, p[t2+1], candf);
                    padd_lt(s2, p[t2+2], candf);
                    padd_lt(s3, p[t2+3], candf);
                }
                float S = (s0 + s1) + (s2 + s3);
#pragma unroll
                for (int o = 16; o > 0; o >>= 1)
                    S += __shfl_xor_sync(0xffffffffu, S, o);
                if (S < T) { P = __float_as_uint(candf); G = S; }
            }
            const float Pf = __uint_as_float(P);
            const float K = Z - G;

            float inv = 1.f / (K + 1e-7f * Z);
#pragma unroll
            for (int t2 = 0; t2 < 32; ++t2)
                pfma_ge(acc[t2], p[t2], inv, Pf);
        }
        __syncthreads();                    // select reads done before next head
    }

    // ---- epilogue: partial head-sum row (row = warp) -> g_part[z]
    {
        const int row = r0 + warp;
        size_t base = ((size_t)blockIdx.z << 22) + (((size_t)(b * 1024 + row)) << 10);
#pragma unroll
        for (int c = 0; c < 8; ++c) {
            int j = c * 128 + lane * 4;
            *(float4*)(part + base + j) =
                make_float4(acc[c*4+0], acc[c*4+1], acc[c*4+2], acc[c*4+3]);
        }
    }
}

// ---------------- combine: part0 + part1 -> attn fp32 + bf16 hi/lo ----------
__global__ void combine_kernel(const float* __restrict__ part, float* __restrict__ attn_out,
                               __nv_bfloat16* __restrict__ ahi, __nv_bfloat16* __restrict__ alo) {
    int i = (blockIdx.x * 256 + threadIdx.x) * 4;
    float4 a = *(const float4*)(part + i);
    float4 bb = *(const float4*)(part + (4u << 20) + i);
    float4 v = make_float4((a.x + bb.x) * 0.0625f, (a.y + bb.y) * 0.0625f,
                           (a.z + bb.z) * 0.0625f, (a.w + bb.w) * 0.0625f);
    *(float4*)(attn_out + i) = v;
    __nv_bfloat162 h0, h1, l0, l1;
    h0.x = __float2bfloat16(v.x); h0.y = __float2bfloat16(v.y);
    h1.x = __float2bfloat16(v.z); h1.y = __float2bfloat16(v.w);
    l0.x = __float2bfloat16(v.x - __bfloat162float(h0.x));
    l0.y = __float2bfloat16(v.y - __bfloat162float(h0.y));
    l1.x = __float2bfloat16(v.z - __bfloat162float(h1.x));
    l1.y = __float2bfloat16(v.w - __bfloat162float(h1.y));
    *(__nv_bfloat162*)(ahi + i)     = h0;
    *(__nv_bfloat162*)(ahi + i + 2) = h1;
    *(__nv_bfloat162*)(alo + i)     = l0;
    *(__nv_bfloat162*)(alo + i + 2) = l1;
}

// ---------------- Launch ------------------------------------------------------
extern "C" void kernel_launch(void* const* d_in, const int* in_sizes, int n_in,
                              void* d_out, int out_size) {
    const float* q     = (const float*)d_in[0];
    const float* k     = (const float*)d_in[1];
    const float* v     = (const float*)d_in[2];
    const float* Wq    = (const float*)d_in[3];
    const float* Wk    = (const float*)d_in[4];
    const int*   kmask = (const int*)d_in[5];
    float*       out   = (float*)d_out;

    __nv_bfloat16 *inhi, *inlo, *whi, *wlo, *pphi, *pplo, *athi, *atlo, *vthi, *vtlo;
    float* partp;
    cudaGetSymbolAddress((void**)&inhi, g_inhi);
    cudaGetSymbolAddress((void**)&inlo, g_inlo);
    cudaGetSymbolAddress((void**)&whi,  g_whi);
    cudaGetSymbolAddress((void**)&wlo,  g_wlo);
    cudaGetSymbolAddress((void**)&pphi, g_pphi);
    cudaGetSymbolAddress((void**)&pplo, g_pplo);
    cudaGetSymbolAddress((void**)&partp, g_part);
    cudaGetSymbolAddress((void**)&athi, g_athi);
    cudaGetSymbolAddress((void**)&atlo, g_atlo);
    cudaGetSymbolAddress((void**)&vthi, g_vthi);
    cudaGetSymbolAddress((void**)&vtlo, g_vtlo);

    cudaFuncSetAttribute(mma_gemm<0>, cudaFuncAttributeMaxDynamicSharedMemorySize, GEMM_SMEM);
    cudaFuncSetAttribute(mma_gemm<1>, cudaFuncAttributeMaxDynamicSharedMemorySize, GEMM_SMEM);
    cudaFuncSetAttribute(attn_fused,  cudaFuncAttributeMaxDynamicSharedMemorySize, FUSED_SMEM);

    const size_t M4 = 4u << 20, M1 = 1u << 20;

    // 1: all four splits (fold 1/sqrt(Dh)=0.125 into q)
    split4_kernel<<<dim3(4096, 4), 256>>>(q, k, Wq, Wk, inhi, inlo, whi, wlo);

    // 2: v -> vT hi/lo
    transpose_split_v<<<dim3(32, 32, 4), 256>>>(v, vthi, vtlo);

    // 3: projections z=0 -> qp, z=1 -> kp, bf16 hi/lo out
    mma_gemm<1><<<dim3(8, 32, 2), 256, GEMM_SMEM>>>(
        inhi, inlo, whi, wlo, nullptr, pphi, pplo, M4, M1, M4, 1024);

    // 4 (profiled launch): fused scores + select, head-split (z = head half)
    attn_fused<<<dim3(64, 4, 2), 512, FUSED_SMEM>>>(
        pphi, pplo, pphi + M4, pplo + M4, kmask, partp);

    // 5: combine halves -> attn fp32 (d_out) + bf16 hi/lo
    combine_kernel<<<4096, 256>>>(partp, out + M4, athi, atlo);

    // 6: out = attn @ vT^T (z = batch)
    mma_gemm<0><<<dim3(8, 8, 4), 256, GEMM_SMEM>>>(
        athi, atlo, vthi, vtlo, out, nullptr, nullptr, M1, M1, M1, 1024);
}

// round 16
// speedup vs baseline: 1.0569x; 1.0569x over previous
#include <cuda_runtime.h>
#include <cuda_bf16.h>
#include <math.h>
#include <float.h>
#include <stdint.h>

// B=4, Sq=Skv=1024, H=16, Dh=64. d_out: [out 4M][attn 4M] fp32.
// Tensor work via baseline-PTX mma.sync (HMMA): tcgen05 unavailable (harness
// compiles through virtual arch compute_103, no 'a' suffix).

__device__ __nv_bfloat16 g_inhi[8u << 20], g_inlo[8u << 20];  // q(scaled)|k
__device__ __nv_bfloat16 g_whi[2u << 20],  g_wlo[2u << 20];   // Wq|Wk
__device__ __nv_bfloat16 g_pphi[8u << 20], g_pplo[8u << 20];  // qp|kp hi/lo
__device__ __nv_bfloat16 g_athi[4u << 20], g_atlo[4u << 20];  // attn hi/lo
__device__ __nv_bfloat16 g_vthi[4u << 20], g_vtlo[4u << 20];  // v^T hi/lo

// ---------------- helpers ----------------------------------------------------
__device__ __forceinline__ uint32_t smem_u32(const void* p) {
    uint32_t a;
    asm("{ .reg .u64 t; cvta.to.shared.u64 t, %1; cvt.u32.u64 %0, t; }" : "=r"(a) : "l"(p));
    return a;
}
__device__ __forceinline__ void mma16816(float* c, const uint32_t* a, const uint32_t* b) {
    asm volatile(
        "mma.sync.aligned.m16n8k16.row.col.f32.bf16.bf16.f32 "
        "{%0,%1,%2,%3}, {%4,%5,%6,%7}, {%8,%9}, {%0,%1,%2,%3};"
        : "+f"(c[0]), "+f"(c[1]), "+f"(c[2]), "+f"(c[3])
        : "r"(a[0]), "r"(a[1]), "r"(a[2]), "r"(a[3]), "r"(b[0]), "r"(b[1]));
}
__device__ __forceinline__ void ldmA(uint32_t* r, uint32_t base, int row0, int kb, int lane) {
    int sub = lane >> 3, rr = lane & 7;
    int row = row0 + rr + ((sub & 1) << 3);
    int ch  = kb + (sub >> 1);
    uint32_t addr = base + row * 128 + ((ch ^ (row & 7)) << 4);
    asm volatile("ldmatrix.sync.aligned.m8n8.x4.shared.b16 {%0,%1,%2,%3}, [%4];"
                 : "=r"(r[0]), "=r"(r[1]), "=r"(r[2]), "=r"(r[3]) : "r"(addr));
}
__device__ __forceinline__ void ldmB(uint32_t* r, uint32_t base, int row0, int kb, int lane) {
    int sub = lane >> 3, rr = lane & 7;
    int row = row0 + rr + ((sub >> 1) << 3);
    int ch  = kb + (sub & 1);
    uint32_t addr = base + row * 128 + ((ch ^ (row & 7)) << 4);
    asm volatile("ldmatrix.sync.aligned.m8n8.x4.shared.b16 {%0,%1,%2,%3}, [%4];"
                 : "=r"(r[0]), "=r"(r[1]), "=r"(r[2]), "=r"(r[3]) : "r"(addr));
}
// predicated integer accumulation for the radix sweep
__device__ __forceinline__ void uadd_lt(uint32_t& s, uint32_t v, uint32_t c) {
    asm("{ .reg .pred q; setp.lt.u32 q, %1, %2; @q add.u32 %0, %0, %1; }"
        : "+r"(s) : "r"(v), "r"(c));
}
// acc += float(u) * inv  if u >= U
__device__ __forceinline__ void pfma_ge_u(float& a, uint32_t u, float inv, uint32_t U) {
    asm("{ .reg .pred q; .reg .f32 f; setp.ge.u32 q, %1, %3; cvt.rn.f32.u32 f, %1;\n\t"
        "@q fma.rn.f32 %0, f, %2, %0; }"
        : "+f"(a) : "r"(u), "f"(inv), "r"(U));
}
__device__ __forceinline__ uint32_t redux_add(uint32_t v) {
    uint32_t r;
    asm("redux.sync.add.u32 %0, %1, 0xffffffff;" : "=r"(r) : "r"(v));
    return r;
}
#define CP_ASYNC16(dst, src) \
    asm volatile("cp.async.cg.shared.global [%0], [%1], 16;" :: "r"(dst), "l"(src))
#define CP_COMMIT() asm volatile("cp.async.commit_group;" ::: "memory")
#define CP_WAIT0()  asm volatile("cp.async.wait_group 0;" ::: "memory")
#define CP_WAIT1()  asm volatile("cp.async.wait_group 1;" ::: "memory")
#define BARG(id)    asm volatile("bar.sync %0, 256;" :: "r"(id) : "memory")

// ---------------- split fp32 -> bf16 hi/lo, all four sources in one launch ---
__global__ void split4_kernel(const float* __restrict__ q, const float* __restrict__ k,
                              const float* __restrict__ Wq, const float* __restrict__ Wk,
                              __nv_bfloat16* __restrict__ inhi, __nv_bfloat16* __restrict__ inlo,
                              __nv_bfloat16* __restrict__ whi,  __nv_bfloat16* __restrict__ wlo) {
    const int y = blockIdx.y;
    int i = (blockIdx.x * 256 + threadIdx.x) * 4;
    const float* in;
    __nv_bfloat16 *hi, *lo;
    size_t off;
    float scale = 1.0f;
    if (y == 0)      { in = q;  hi = inhi; lo = inlo; off = 0;        scale = 0.125f; }
    else if (y == 1) { in = k;  hi = inhi; lo = inlo; off = 4u << 20; }
    else if (y == 2) { if (i >= (1 << 20)) return; in = Wq; hi = whi; lo = wlo; off = 0; }
    else             { if (i >= (1 << 20)) return; in = Wk; hi = whi; lo = wlo; off = 1u << 20; }
    float4 v = *(const float4*)(in + i);
    v.x *= scale; v.y *= scale; v.z *= scale; v.w *= scale;
    __nv_bfloat162 H0, H1, L0, L1;
    H0.x = __float2bfloat16(v.x); H0.y = __float2bfloat16(v.y);
    H1.x = __float2bfloat16(v.z); H1.y = __float2bfloat16(v.w);
    L0.x = __float2bfloat16(v.x - __bfloat162float(H0.x));
    L0.y = __float2bfloat16(v.y - __bfloat162float(H0.y));
    L1.x = __float2bfloat16(v.z - __bfloat162float(H1.x));
    L1.y = __float2bfloat16(v.w - __bfloat162float(H1.y));
    *(__nv_bfloat162*)(hi + off + i)     = H0;
    *(__nv_bfloat162*)(hi + off + i + 2) = H1;
    *(__nv_bfloat162*)(lo + off + i)     = L0;
    *(__nv_bfloat162*)(lo + off + i + 2) = L1;
}

// ---------------- v[b][k][n] -> vT hi/lo [b][n][k] ---------------------------
__global__ __launch_bounds__(256)
void transpose_split_v(const float* __restrict__ v, __nv_bfloat16* __restrict__ thi,
                       __nv_bfloat16* __restrict__ tlo) {
    __shared__ float tile[32][33];
    const int b = blockIdx.z, n0 = blockIdx.x * 32, k0 = blockIdx.y * 32;
    const int tx = threadIdx.x & 31, ty = threadIdx.x >> 5;
    const float* I = v + ((size_t)b << 20);
#pragma unroll
    for (int i = 0; i < 4; ++i)
        tile[ty + i * 8][tx] = I[(size_t)(k0 + ty + i * 8) * 1024 + n0 + tx];
    __syncthreads();
#pragma unroll
    for (int i = 0; i < 4; ++i) {
        float x = tile[tx][ty + i * 8];
        size_t o = ((size_t)b << 20) + (size_t)(n0 + ty + i * 8) * 1024 + k0 + tx;
        __nv_bfloat16 h = __float2bfloat16(x);
        thi[o] = h;
        tlo[o] = __float2bfloat16(x - __bfloat162float(h));
    }
}

// ---------------- split-bf16 NT GEMM via mma.sync ----------------------------
// Single 64KB stage buffer + __launch_bounds__(256,2) -> 2 CTAs/SM.
#define GEMM_SMEM 65536
template <int BF16OUT>
__global__ __launch_bounds__(256, 2)
void mma_gemm(const __nv_bfloat16* __restrict__ Ahi, const __nv_bfloat16* __restrict__ Alo,
              const __nv_bfloat16* __restrict__ Bhi, const __nv_bfloat16* __restrict__ Blo,
              float* __restrict__ Cf, __nv_bfloat16* __restrict__ Chi,
              __nv_bfloat16* __restrict__ Clo,
              size_t aMulZ, size_t bMulZ, size_t cMulZ, int K) {
    extern __shared__ char smem[];
    const uint32_t sb = smem_u32(smem);
    const int tid = threadIdx.x, wid = tid >> 5, lane = tid & 31;
    const int m0 = blockIdx.y * 128, n0 = blockIdx.x * 128, z = blockIdx.z;
    const int wm = wid >> 2, wn = wid & 3;

    const __nv_bfloat16* srcs[4] = {
        Ahi + (size_t)z * aMulZ + (size_t)m0 * 1024, Alo + (size_t)z * aMulZ + (size_t)m0 * 1024,
        Bhi + (size_t)z * bMulZ + (size_t)n0 * 1024, Blo + (size_t)z * bMulZ + (size_t)n0 * 1024 };
    const size_t coff = (size_t)z * cMulZ;

    float acc[4][4][4];
#pragma unroll
    for (int i = 0; i < 4; ++i)
#pragma unroll
        for (int j = 0; j < 4; ++j)
#pragma unroll
            for (int e = 0; e < 4; ++e) acc[i][j][e] = 0.f;

    const int lrow = tid >> 3, lc = tid & 7;
    const int nstage = K >> 6;

    {   // prefetch stage 0
#pragma unroll
        for (int mat = 0; mat < 4; ++mat) {
            const __nv_bfloat16* sp = srcs[mat] + lc * 8;
#pragma unroll
            for (int i = 0; i < 4; ++i) {
                int row = lrow + i * 32;
                uint32_t dst = sb + mat * 16384 + row * 128 + ((lc ^ (row & 7)) << 4);
                CP_ASYNC16(dst, sp + (size_t)row * 1024);
            }
        }
        CP_COMMIT();
    }

    for (int s = 0; s < nstage; ++s) {
        CP_WAIT0();
        __syncthreads();
#pragma unroll
        for (int ks = 0; ks < 4; ++ks) {
            const int kb = ks * 2;
            uint32_t ah[4][4], al[4][4];
#pragma unroll
            for (int fm = 0; fm < 4; ++fm) {
                ldmA(ah[fm], sb,         wm * 64 + fm * 16, kb, lane);
                ldmA(al[fm], sb + 16384, wm * 64 + fm * 16, kb, lane);
            }
#pragma unroll
            for (int nh = 0; nh < 2; ++nh) {
                uint32_t bh[4], bl[4];
                ldmB(bh, sb + 32768, wn * 32 + nh * 16, kb, lane);
                ldmB(bl, sb + 49152, wn * 32 + nh * 16, kb, lane);
#pragma unroll
                for (int fm = 0; fm < 4; ++fm) {
                    mma16816(acc[fm][2 * nh],     ah[fm], bh);
                    mma16816(acc[fm][2 * nh],     al[fm], bh);
                    mma16816(acc[fm][2 * nh],     ah[fm], bl);
                    mma16816(acc[fm][2 * nh + 1], ah[fm], bh + 2);
                    mma16816(acc[fm][2 * nh + 1], al[fm], bh + 2);
                    mma16816(acc[fm][2 * nh + 1], ah[fm], bl + 2);
                }
            }
        }
        __syncthreads();
        if (s + 1 < nstage) {
            const int k1 = (s + 1) << 6;
#pragma unroll
            for (int mat = 0; mat < 4; ++mat) {
                const __nv_bfloat16* sp = srcs[mat] + k1 + lc * 8;
#pragma unroll
                for (int i = 0; i < 4; ++i) {
                    int row = lrow + i * 32;
                    uint32_t dst = sb + mat * 16384 + row * 128 + ((lc ^ (row & 7)) << 4);
                    CP_ASYNC16(dst, sp + (size_t)row * 1024);
                }
            }
            CP_COMMIT();
        }
    }

    const int g = lane >> 2, tig = lane & 3;
#pragma unroll
    for (int fm = 0; fm < 4; ++fm)
#pragma unroll
        for (int j = 0; j < 4; ++j) {
            int row = m0 + wm * 64 + fm * 16 + g;
            int col = n0 + wn * 32 + j * 8 + 2 * tig;
            float d0 = acc[fm][j][0], d1 = acc[fm][j][1];
            float d2 = acc[fm][j][2], d3 = acc[fm][j][3];
            if (BF16OUT) {
                __nv_bfloat162 h0, l0, h1, l1;
                h0.x = __float2bfloat16(d0); h0.y = __float2bfloat16(d1);
                l0.x = __float2bfloat16(d0 - __bfloat162float(h0.x));
                l0.y = __float2bfloat16(d1 - __bfloat162float(h0.y));
                h1.x = __float2bfloat16(d2); h1.y = __float2bfloat16(d3);
                l1.x = __float2bfloat16(d2 - __bfloat162float(h1.x));
                l1.y = __float2bfloat16(d3 - __bfloat162float(h1.y));
                *(__nv_bfloat162*)(Chi + coff + (size_t)row * 1024 + col)       = h0;
                *(__nv_bfloat162*)(Clo + coff + (size_t)row * 1024 + col)       = l0;
                *(__nv_bfloat162*)(Chi + coff + (size_t)(row + 8) * 1024 + col) = h1;
                *(__nv_bfloat162*)(Clo + coff + (size_t)(row + 8) * 1024 + col) = l1;
            } else {
                *(float2*)(Cf + coff + (size_t)row * 1024 + col)       = make_float2(d0, d1);
                *(float2*)(Cf + coff + (size_t)(row + 8) * 1024 + col) = make_float2(d2, d3);
            }
        }
}

// ---------------- fused scores-MMA + thresholded softmax + head mean --------
// R14 structure (proven 514.1): CTA = (b, 16 q-rows), 512 thr / 16 warps,
// two chunk groups with named barriers + per-group kp double buffer.
// Changes: (a) mask applied WRITER-side at MMA scatter; (b) select uses an
// integer radix (u = rint(p*2^19), Sigma/S via redux.sync.add.u32 — one
// ~25cyc instruction replaces the 5-deep shfl tree per round), 20 rounds
// (bits 19..0) resolve the cutoff exactly in the integer domain.
#define SCW 1036
#define F_QP 0                       // 2 groups x 4KB
#define F_KP 8192                    // 2 groups x 2 bufs x 32KB
#define F_SC (8192 + 131072)
#define F_KM (F_SC + 16 * SCW * 4)
#define FUSED_SMEM (F_KM + 1024)

__global__ __launch_bounds__(512, 1)
void attn_fused(const __nv_bfloat16* __restrict__ qphi, const __nv_bfloat16* __restrict__ qplo,
                const __nv_bfloat16* __restrict__ kphi, const __nv_bfloat16* __restrict__ kplo,
                const int* __restrict__ kmask, float* __restrict__ attn_out,
                __nv_bfloat16* __restrict__ ahi, __nv_bfloat16* __restrict__ alo) {
    extern __shared__ char smem[];
    const uint32_t sb = smem_u32(smem);
    const int b = blockIdx.y, r0 = blockIdx.x * 16;
    const int tid = threadIdx.x, warp = tid >> 5, lane = tid & 31;
    const int g = warp >> 3, gw = warp & 7, gtid = tid & 255;
    float* sc = (float*)(smem + F_SC);
    unsigned char* km = (unsigned char*)(smem + F_KM);

    const uint32_t myqp = sb + F_QP + g * 4096;
    const uint32_t kp0  = sb + F_KP + g * 65536;          // buffer 0
    const uint32_t kp1  = kp0 + 32768;                    // buffer 1

    for (int i = tid; i < 1024; i += 512)
        km[i] = (kmask[b * 1024 + i] > 0) ? 1 : 0;

    float acc[32];
#pragma unroll
    for (int t2 = 0; t2 < 32; ++t2) acc[t2] = 0.f;

    const int qmat = gtid >> 7, qrow = (gtid >> 3) & 15, qlc = gtid & 7;
    const int lrow = gtid >> 3, lc = gtid & 7;

    auto stage_qp = [&](int h) {
        const __nv_bfloat16* qsrc = (qmat ? qplo : qphi)
            + (size_t)(b * 1024 + r0 + qrow) * 1024 + h * 64 + qlc * 8;
        CP_ASYNC16(myqp + qmat * 2048 + qrow * 128 + ((qlc ^ (qrow & 7)) << 4), qsrc);
    };
    auto stage_chunk = [&](int h, int c, uint32_t buf) {
#pragma unroll
        for (int mat = 0; mat < 2; ++mat) {
            const __nv_bfloat16* base = mat ? kplo : kphi;
#pragma unroll
            for (int i = 0; i < 4; ++i) {
                int row = lrow + i * 32;
                const __nv_bfloat16* src = base
                    + (size_t)(b * 1024 + c * 128 + row) * 1024 + h * 64 + lc * 8;
                CP_ASYNC16(buf + mat * 16384 + row * 128 + ((lc ^ (row & 7)) << 4), src);
            }
        }
    };

    stage_qp(0);
    stage_chunk(0, g, kp0);
    CP_COMMIT();
    __syncthreads();               // km visible to both groups before scatter

    for (int h = 0; h < 16; ++h) {
        uint32_t ah[4][4], al[4][4];
        for (int ci = 0; ci < 4; ++ci) {
            const int c = g + 2 * ci;                   // this group's chunk
            const uint32_t nbuf = ((ci + 1) & 1) ? kp1 : kp0;
            if (ci < 3) {
                stage_chunk(h, c + 2, nbuf);
                CP_COMMIT();
            } else if (h < 15) {
                stage_qp(h + 1);
                stage_chunk(h + 1, g, nbuf);
                CP_COMMIT();
            }
            if (h == 15 && ci == 3) CP_WAIT0(); else CP_WAIT1();
            BARG(g + 1);                                // chunk c resident for group
            if (ci == 0) {
#pragma unroll
                for (int ks = 0; ks < 4; ++ks) {
                    ldmA(ah[ks], myqp,        0, 2 * ks, lane);
                    ldmA(al[ks], myqp + 2048, 0, 2 * ks, lane);
                }
            }
            const uint32_t cbuf = (ci & 1) ? kp1 : kp0;
            float c0a[4] = {0.f,0.f,0.f,0.f}, c0b[4] = {0.f,0.f,0.f,0.f};
            float c1a[4] = {0.f,0.f,0.f,0.f}, c1b[4] = {0.f,0.f,0.f,0.f};
#pragma unroll
            for (int ks = 0; ks < 4; ++ks) {
                uint32_t bh[4], bl[4];
                ldmB(bh, cbuf,         gw * 16, 2 * ks, lane);
                ldmB(bl, cbuf + 16384, gw * 16, 2 * ks, lane);
                mma16816(c0a, ah[ks], bh);
                mma16816(c0b, al[ks], bh);
                mma16816(c0b, ah[ks], bl);
                mma16816(c1a, ah[ks], bh + 2);
                mma16816(c1b, al[ks], bh + 2);
                mma16816(c1b, ah[ks], bl + 2);
            }
            {   // scatter this chunk's 16x16 score tile, mask applied here
                int gr = lane >> 2, tig = lane & 3;
                int colb = c * 128 + gw * 16 + 2 * tig;
                float k0f = km[colb]     ? 0.f : -FLT_MAX;
                float k1f = km[colb + 1] ? 0.f : -FLT_MAX;
                float k8f = km[colb + 8] ? 0.f : -FLT_MAX;
                float k9f = km[colb + 9] ? 0.f : -FLT_MAX;
                *(float2*)&sc[gr * SCW + colb] =
                    make_float2(k0f + (c0a[0]+c0b[0]), k1f + (c0a[1]+c0b[1]));
                *(float2*)&sc[(gr + 8) * SCW + colb] =
                    make_float2(k0f + (c0a[2]+c0b[2]), k1f + (c0a[3]+c0b[3]));
                *(float2*)&sc[gr * SCW + colb + 8] =
                    make_float2(k8f + (c1a[0]+c1b[0]), k9f + (c1a[1]+c1b[1]));
                *(float2*)&sc[(gr + 8) * SCW + colb + 8] =
                    make_float2(k8f + (c1a[2]+c1b[2]), k9f + (c1a[3]+c1b[3]));
            }
            BARG(g + 1);                                // group done reading cbuf
        }
        __syncthreads();                                // sc complete from both groups

        // ---- select: one row per warp (row = warp); sc already masked
        {
            const int row = warp;
            float pv[32];
            float m = -FLT_MAX;
#pragma unroll
            for (int c = 0; c < 8; ++c) {
                int j = c * 128 + lane * 4;
                float4 v = *(const float4*)&sc[row * SCW + j];
                pv[c*4+0] = v.x; pv[c*4+1] = v.y; pv[c*4+2] = v.z; pv[c*4+3] = v.w;
                m = fmaxf(m, fmaxf(fmaxf(v.x, v.y), fmaxf(v.z, v.w)));
            }
#pragma unroll
            for (int o = 16; o > 0; o >>= 1)
                m = fmaxf(m, __shfl_xor_sync(0xffffffffu, m, o));

            // quantize p = exp(x - m) in [0,1] to u = rint(p * 2^19)
            uint32_t u[32];
            uint32_t l0 = 0, l1 = 0, l2 = 0, l3 = 0;
#pragma unroll
            for (int t2 = 0; t2 < 32; t2 += 4) {
                u[t2+0] = __float2uint_rn(__expf(pv[t2+0] - m) * 524288.f); l0 += u[t2+0];
                u[t2+1] = __float2uint_rn(__expf(pv[t2+1] - m) * 524288.f); l1 += u[t2+1];
                u[t2+2] = __float2uint_rn(__expf(pv[t2+2] - m) * 524288.f); l2 += u[t2+2];
                u[t2+3] = __float2uint_rn(__expf(pv[t2+3] - m) * 524288.f); l3 += u[t2+3];
            }
            const uint32_t Sigma = redux_add((l0 + l1) + (l2 + l3));   // Sigma <= 2^24

            // integer radix select: U = first value where inclusive cumsum
            // reaches T = Sigma/10 (criterion 10*S < Sigma, exact; 10S < 2^28).
            // Invariant: G = sum(u < U) < T. 20 rounds (u <= 2^19) -> exact.
            uint32_t U = 0, G = 0;
            for (int bit = 19; bit >= 0; --bit) {
                const uint32_t cand = U + (1u << bit);
                uint32_t s0 = 0, s1 = 0, s2 = 0, s3 = 0;
#pragma unroll
                for (int t2 = 0; t2 < 32; t2 += 4) {
                    uadd_lt(s0, u[t2+0], cand);
                    uadd_lt(s1, u[t2+1], cand);
                    uadd_lt(s2, u[t2+2], cand);
                    uadd_lt(s3, u[t2+3], cand);
                }
                const uint32_t S = redux_add((s0 + s1) + (s2 + s3));
                if (S * 10u < Sigma) { U = cand; G = S; }
            }

            // kept mass K = Sigma - G (exact int); norm = u*2^-19 / (K' + eps*Z)
            const float Zf = (float)Sigma * (1.f / 524288.f);
            const float Kf = (float)(Sigma - G) * (1.f / 524288.f);
            const float inv = (1.f / 524288.f) / (Kf + 1e-7f * Zf);
#pragma unroll
            for (int t2 = 0; t2 < 32; ++t2)
                pfma_ge_u(acc[t2], u[t2], inv, U);
        }
        __syncthreads();                    // select reads done before next head
    }

    // ---- epilogue: head-mean row (row = warp) -> attn fp32 + bf16 hi/lo
    {
        const int row = r0 + warp;
        size_t base = ((size_t)(b * 1024 + row)) << 10;
#pragma unroll
        for (int c = 0; c < 8; ++c) {
            int j = c * 128 + lane * 4;
            float4 v = make_float4(acc[c*4+0] * 0.0625f, acc[c*4+1] * 0.0625f,
                                   acc[c*4+2] * 0.0625f, acc[c*4+3] * 0.0625f);
            *(float4*)(attn_out + base + j) = v;
            __nv_bfloat162 h0, h1, l0, l1;
            h0.x = __float2bfloat16(v.x); h0.y = __float2bfloat16(v.y);
            h1.x = __float2bfloat16(v.z); h1.y = __float2bfloat16(v.w);
            l0.x = __float2bfloat16(v.x - __bfloat162float(h0.x));
            l0.y = __float2bfloat16(v.y - __bfloat162float(h0.y));
            l1.x = __float2bfloat16(v.z - __bfloat162float(h1.x));
            l1.y = __float2bfloat16(v.w - __bfloat162float(h1.y));
            *(__nv_bfloat162*)(ahi + base + j)     = h0;
            *(__nv_bfloat162*)(ahi + base + j + 2) = h1;
            *(__nv_bfloat162*)(alo + base + j)     = l0;
            *(__nv_bfloat162*)(alo + base + j + 2) = l1;
        }
    }
}

// ---------------- Launch ------------------------------------------------------
extern "C" void kernel_launch(void* const* d_in, const int* in_sizes, int n_in,
                              void* d_out, int out_size) {
    const float* q     = (const float*)d_in[0];
    const float* k     = (const float*)d_in[1];
    const float* v     = (const float*)d_in[2];
    const float* Wq    = (const float*)d_in[3];
    const float* Wk    = (const float*)d_in[4];
    const int*   kmask = (const int*)d_in[5];
    float*       out   = (float*)d_out;

    __nv_bfloat16 *inhi, *inlo, *whi, *wlo, *pphi, *pplo, *athi, *atlo, *vthi, *vtlo;
    cudaGetSymbolAddress((void**)&inhi, g_inhi);
    cudaGetSymbolAddress((void**)&inlo, g_inlo);
    cudaGetSymbolAddress((void**)&whi,  g_whi);
    cudaGetSymbolAddress((void**)&wlo,  g_wlo);
    cudaGetSymbolAddress((void**)&pphi, g_pphi);
    cudaGetSymbolAddress((void**)&pplo, g_pplo);
    cudaGetSymbolAddress((void**)&athi, g_athi);
    cudaGetSymbolAddress((void**)&atlo, g_atlo);
    cudaGetSymbolAddress((void**)&vthi, g_vthi);
    cudaGetSymbolAddress((void**)&vtlo, g_vtlo);

    cudaFuncSetAttribute(mma_gemm<0>, cudaFuncAttributeMaxDynamicSharedMemorySize, GEMM_SMEM);
    cudaFuncSetAttribute(mma_gemm<1>, cudaFuncAttributeMaxDynamicSharedMemorySize, GEMM_SMEM);
    cudaFuncSetAttribute(attn_fused,  cudaFuncAttributeMaxDynamicSharedMemorySize, FUSED_SMEM);

    const size_t M4 = 4u << 20, M1 = 1u << 20;

    // 1: all four splits (fold 1/sqrt(Dh)=0.125 into q)
    split4_kernel<<<dim3(4096, 4), 256>>>(q, k, Wq, Wk, inhi, inlo, whi, wlo);

    // 2: v -> vT hi/lo
    transpose_split_v<<<dim3(32, 32, 4), 256>>>(v, vthi, vtlo);

    // 3: projections z=0 -> qp, z=1 -> kp, bf16 hi/lo out
    mma_gemm<1><<<dim3(8, 32, 2), 256, GEMM_SMEM>>>(
        inhi, inlo, whi, wlo, nullptr, pphi, pplo, M4, M1, M4, 1024);

    // 4 (profiled launch): fused scores + thresholded softmax + head mean
    attn_fused<<<dim3(64, 4), 512, FUSED_SMEM>>>(
        pphi, pplo, pphi + M4, pplo + M4, kmask, out + M4, athi, atlo);

    // 5: out = attn @ vT^T (z = batch)
    mma_gemm<0><<<dim3(8, 8, 4), 256, GEMM_SMEM>>>(
        athi, atlo, vthi, vtlo, out, nullptr, nullptr, M1, M1, M1, 1024);
}

// round 17
// speedup vs baseline: 1.0575x; 1.0006x over previous
#include <cuda_runtime.h>
#include <cuda_bf16.h>
#include <math.h>
#include <float.h>
#include <stdint.h>

// B=4, Sq=Skv=1024, H=16, Dh=64. d_out: [out 4M][attn 4M] fp32.
// Tensor work via baseline-PTX mma.sync (HMMA): tcgen05 unavailable (harness
// compiles through virtual arch compute_103, no 'a' suffix).

__device__ __nv_bfloat16 g_inhi[8u << 20], g_inlo[8u << 20];  // q(scaled)|k
__device__ __nv_bfloat16 g_whi[2u << 20],  g_wlo[2u << 20];   // Wq|Wk
__device__ __nv_bfloat16 g_pphi[8u << 20], g_pplo[8u << 20];  // qp|kp hi/lo
__device__ __nv_bfloat16 g_athi[4u << 20], g_atlo[4u << 20];  // attn hi/lo
__device__ __nv_bfloat16 g_vthi[4u << 20], g_vtlo[4u << 20];  // v^T hi/lo

// ---------------- helpers ----------------------------------------------------
__device__ __forceinline__ uint32_t smem_u32(const void* p) {
    uint32_t a;
    asm("{ .reg .u64 t; cvta.to.shared.u64 t, %1; cvt.u32.u64 %0, t; }" : "=r"(a) : "l"(p));
    return a;
}
__device__ __forceinline__ void mma16816(float* c, const uint32_t* a, const uint32_t* b) {
    asm volatile(
        "mma.sync.aligned.m16n8k16.row.col.f32.bf16.bf16.f32 "
        "{%0,%1,%2,%3}, {%4,%5,%6,%7}, {%8,%9}, {%0,%1,%2,%3};"
        : "+f"(c[0]), "+f"(c[1]), "+f"(c[2]), "+f"(c[3])
        : "r"(a[0]), "r"(a[1]), "r"(a[2]), "r"(a[3]), "r"(b[0]), "r"(b[1]));
}
__device__ __forceinline__ void ldmA(uint32_t* r, uint32_t base, int row0, int kb, int lane) {
    int sub = lane >> 3, rr = lane & 7;
    int row = row0 + rr + ((sub & 1) << 3);
    int ch  = kb + (sub >> 1);
    uint32_t addr = base + row * 128 + ((ch ^ (row & 7)) << 4);
    asm volatile("ldmatrix.sync.aligned.m8n8.x4.shared.b16 {%0,%1,%2,%3}, [%4];"
                 : "=r"(r[0]), "=r"(r[1]), "=r"(r[2]), "=r"(r[3]) : "r"(addr));
}
__device__ __forceinline__ void ldmB(uint32_t* r, uint32_t base, int row0, int kb, int lane) {
    int sub = lane >> 3, rr = lane & 7;
    int row = row0 + rr + ((sub >> 1) << 3);
    int ch  = kb + (sub & 1);
    uint32_t addr = base + row * 128 + ((ch ^ (row & 7)) << 4);
    asm volatile("ldmatrix.sync.aligned.m8n8.x4.shared.b16 {%0,%1,%2,%3}, [%4];"
                 : "=r"(r[0]), "=r"(r[1]), "=r"(r[2]), "=r"(r[3]) : "r"(addr));
}
// predicated integer accumulation for the radix sweep
__device__ __forceinline__ void uadd_lt(uint32_t& s, uint32_t v, uint32_t c) {
    asm("{ .reg .pred q; setp.lt.u32 q, %1, %2; @q add.u32 %0, %0, %1; }"
        : "+r"(s) : "r"(v), "r"(c));
}
// acc += float(u) * inv  if u >= U
__device__ __forceinline__ void pfma_ge_u(float& a, uint32_t u, float inv, uint32_t U) {
    asm("{ .reg .pred q; .reg .f32 f; setp.ge.u32 q, %1, %3; cvt.rn.f32.u32 f, %1;\n\t"
        "@q fma.rn.f32 %0, f, %2, %0; }"
        : "+f"(a) : "r"(u), "f"(inv), "r"(U));
}
__device__ __forceinline__ uint32_t redux_add(uint32_t v) {
    uint32_t r;
    asm("redux.sync.add.u32 %0, %1, 0xffffffff;" : "=r"(r) : "r"(v));
    return r;
}
__device__ __forceinline__ uint32_t redux_max(uint32_t v) {
    uint32_t r;
    asm("redux.sync.max.u32 %0, %1, 0xffffffff;" : "=r"(r) : "r"(v));
    return r;
}
// warp-max of a float via monotone map + redux.sync.max.u32 (no NaNs present)
__device__ __forceinline__ float warp_fmax(float x) {
    uint32_t bu = __float_as_uint(x);
    uint32_t key = ((int)bu < 0) ? ~bu : (bu | 0x80000000u);
    key = redux_max(key);
    bu = ((int)key < 0) ? ~key : (key ^ 0x80000000u);
    // note: key top bit 0 -> original negative -> bits = ~key
    //       key top bit 1 -> original non-neg -> bits = key ^ 0x80000000
    return __uint_as_float(bu);
}
#define CP_ASYNC16(dst, src) \
    asm volatile("cp.async.cg.shared.global [%0], [%1], 16;" :: "r"(dst), "l"(src))
#define CP_COMMIT() asm volatile("cp.async.commit_group;" ::: "memory")
#define CP_WAIT0()  asm volatile("cp.async.wait_group 0;" ::: "memory")
#define CP_WAIT1()  asm volatile("cp.async.wait_group 1;" ::: "memory")
#define BARG(id)    asm volatile("bar.sync %0, 256;" :: "r"(id) : "memory")

// ---------------- prep: all 4 splits + v-transpose in ONE launch -------------
// blocks [0,4096) q-split, [4096,8192) k-split, [8192,9216) Wq, [9216,10240) Wk,
// [10240,14336) v -> vT hi/lo transpose.
__global__ __launch_bounds__(256)
void prep_kernel(const float* __restrict__ q, const float* __restrict__ k,
                 const float* __restrict__ Wq, const float* __restrict__ Wk,
                 const float* __restrict__ v,
                 __nv_bfloat16* __restrict__ inhi, __nv_bfloat16* __restrict__ inlo,
                 __nv_bfloat16* __restrict__ whi,  __nv_bfloat16* __restrict__ wlo,
                 __nv_bfloat16* __restrict__ vthi, __nv_bfloat16* __restrict__ vtlo) {
    __shared__ float tile[32][33];
    const int bid = blockIdx.x;
    if (bid < 10240) {
        const float* in;
        __nv_bfloat16 *hi, *lo;
        size_t off;
        float scale = 1.0f;
        int i;
        if (bid < 4096)      { i = (bid * 256 + threadIdx.x) * 4;          in = q;  hi = inhi; lo = inlo; off = 0;        scale = 0.125f; }
        else if (bid < 8192) { i = ((bid - 4096) * 256 + threadIdx.x) * 4; in = k;  hi = inhi; lo = inlo; off = 4u << 20; }
        else if (bid < 9216) { i = ((bid - 8192) * 256 + threadIdx.x) * 4; in = Wq; hi = whi;  lo = wlo;  off = 0; }
        else                 { i = ((bid - 9216) * 256 + threadIdx.x) * 4; in = Wk; hi = whi;  lo = wlo;  off = 1u << 20; }
        float4 vv = *(const float4*)(in + i);
        vv.x *= scale; vv.y *= scale; vv.z *= scale; vv.w *= scale;
        __nv_bfloat162 H0, H1, L0, L1;
        H0.x = __float2bfloat16(vv.x); H0.y = __float2bfloat16(vv.y);
        H1.x = __float2bfloat16(vv.z); H1.y = __float2bfloat16(vv.w);
        L0.x = __float2bfloat16(vv.x - __bfloat162float(H0.x));
        L0.y = __float2bfloat16(vv.y - __bfloat162float(H0.y));
        L1.x = __float2bfloat16(vv.z - __bfloat162float(H1.x));
        L1.y = __float2bfloat16(vv.w - __bfloat162float(H1.y));
        *(__nv_bfloat162*)(hi + off + i)     = H0;
        *(__nv_bfloat162*)(hi + off + i + 2) = H1;
        *(__nv_bfloat162*)(lo + off + i)     = L0;
        *(__nv_bfloat162*)(lo + off + i + 2) = L1;
    } else {
        const int t = bid - 10240;
        const int b = t >> 10, rem = t & 1023;
        const int n0 = (rem & 31) * 32, k0 = (rem >> 5) * 32;
        const int tx = threadIdx.x & 31, ty = threadIdx.x >> 5;
        const float* I = v + ((size_t)b << 20);
#pragma unroll
        for (int i = 0; i < 4; ++i)
            tile[ty + i * 8][tx] = I[(size_t)(k0 + ty + i * 8) * 1024 + n0 + tx];
        __syncthreads();
#pragma unroll
        for (int i = 0; i < 4; ++i) {
            float x = tile[tx][ty + i * 8];
            size_t o = ((size_t)b << 20) + (size_t)(n0 + ty + i * 8) * 1024 + k0 + tx;
            __nv_bfloat16 h = __float2bfloat16(x);
            vthi[o] = h;
            vtlo[o] = __float2bfloat16(x - __bfloat162float(h));
        }
    }
}

// ---------------- split-bf16 NT GEMM via mma.sync ----------------------------
// Single 64KB stage buffer + __launch_bounds__(256,2) -> 2 CTAs/SM.
#define GEMM_SMEM 65536
template <int BF16OUT>
__global__ __launch_bounds__(256, 2)
void mma_gemm(const __nv_bfloat16* __restrict__ Ahi, const __nv_bfloat16* __restrict__ Alo,
              const __nv_bfloat16* __restrict__ Bhi, const __nv_bfloat16* __restrict__ Blo,
              float* __restrict__ Cf, __nv_bfloat16* __restrict__ Chi,
              __nv_bfloat16* __restrict__ Clo,
              size_t aMulZ, size_t bMulZ, size_t cMulZ, int K) {
    extern __shared__ char smem[];
    const uint32_t sb = smem_u32(smem);
    const int tid = threadIdx.x, wid = tid >> 5, lane = tid & 31;
    const int m0 = blockIdx.y * 128, n0 = blockIdx.x * 128, z = blockIdx.z;
    const int wm = wid >> 2, wn = wid & 3;

    const __nv_bfloat16* srcs[4] = {
        Ahi + (size_t)z * aMulZ + (size_t)m0 * 1024, Alo + (size_t)z * aMulZ + (size_t)m0 * 1024,
        Bhi + (size_t)z * bMulZ + (size_t)n0 * 1024, Blo + (size_t)z * bMulZ + (size_t)n0 * 1024 };
    const size_t coff = (size_t)z * cMulZ;

    float acc[4][4][4];
#pragma unroll
    for (int i = 0; i < 4; ++i)
#pragma unroll
        for (int j = 0; j < 4; ++j)
#pragma unroll
            for (int e = 0; e < 4; ++e) acc[i][j][e] = 0.f;

    const int lrow = tid >> 3, lc = tid & 7;
    const int nstage = K >> 6;

    {   // prefetch stage 0
#pragma unroll
        for (int mat = 0; mat < 4; ++mat) {
            const __nv_bfloat16* sp = srcs[mat] + lc * 8;
#pragma unroll
            for (int i = 0; i < 4; ++i) {
                int row = lrow + i * 32;
                uint32_t dst = sb + mat * 16384 + row * 128 + ((lc ^ (row & 7)) << 4);
                CP_ASYNC16(dst, sp + (size_t)row * 1024);
            }
        }
        CP_COMMIT();
    }

    for (int s = 0; s < nstage; ++s) {
        CP_WAIT0();
        __syncthreads();
#pragma unroll
        for (int ks = 0; ks < 4; ++ks) {
            const int kb = ks * 2;
            uint32_t ah[4][4], al[4][4];
#pragma unroll
            for (int fm = 0; fm < 4; ++fm) {
                ldmA(ah[fm], sb,         wm * 64 + fm * 16, kb, lane);
                ldmA(al[fm], sb + 16384, wm * 64 + fm * 16, kb, lane);
            }
#pragma unroll
            for (int nh = 0; nh < 2; ++nh) {
                uint32_t bh[4], bl[4];
                ldmB(bh, sb + 32768, wn * 32 + nh * 16, kb, lane);
                ldmB(bl, sb + 49152, wn * 32 + nh * 16, kb, lane);
#pragma unroll
                for (int fm = 0; fm < 4; ++fm) {
                    mma16816(acc[fm][2 * nh],     ah[fm], bh);
                    mma16816(acc[fm][2 * nh],     al[fm], bh);
                    mma16816(acc[fm][2 * nh],     ah[fm], bl);
                    mma16816(acc[fm][2 * nh + 1], ah[fm], bh + 2);
                    mma16816(acc[fm][2 * nh + 1], al[fm], bh + 2);
                    mma16816(acc[fm][2 * nh + 1], ah[fm], bl + 2);
                }
            }
        }
        __syncthreads();
        if (s + 1 < nstage) {
            const int k1 = (s + 1) << 6;
#pragma unroll
            for (int mat = 0; mat < 4; ++mat) {
                const __nv_bfloat16* sp = srcs[mat] + k1 + lc * 8;
#pragma unroll
                for (int i = 0; i < 4; ++i) {
                    int row = lrow + i * 32;
                    uint32_t dst = sb + mat * 16384 + row * 128 + ((lc ^ (row & 7)) << 4);
                    CP_ASYNC16(dst, sp + (size_t)row * 1024);
                }
            }
            CP_COMMIT();
        }
    }

    const int g = lane >> 2, tig = lane & 3;
#pragma unroll
    for (int fm = 0; fm < 4; ++fm)
#pragma unroll
        for (int j = 0; j < 4; ++j) {
            int row = m0 + wm * 64 + fm * 16 + g;
            int col = n0 + wn * 32 + j * 8 + 2 * tig;
            float d0 = acc[fm][j][0], d1 = acc[fm][j][1];
            float d2 = acc[fm][j][2], d3 = acc[fm][j][3];
            if (BF16OUT) {
                __nv_bfloat162 h0, l0, h1, l1;
                h0.x = __float2bfloat16(d0); h0.y = __float2bfloat16(d1);
                l0.x = __float2bfloat16(d0 - __bfloat162float(h0.x));
                l0.y = __float2bfloat16(d1 - __bfloat162float(h0.y));
                h1.x = __float2bfloat16(d2); h1.y = __float2bfloat16(d3);
                l1.x = __float2bfloat16(d2 - __bfloat162float(h1.x));
                l1.y = __float2bfloat16(d3 - __bfloat162float(h1.y));
                *(__nv_bfloat162*)(Chi + coff + (size_t)row * 1024 + col)       = h0;
                *(__nv_bfloat162*)(Clo + coff + (size_t)row * 1024 + col)       = l0;
                *(__nv_bfloat162*)(Chi + coff + (size_t)(row + 8) * 1024 + col) = h1;
                *(__nv_bfloat162*)(Clo + coff + (size_t)(row + 8) * 1024 + col) = l1;
            } else {
                *(float2*)(Cf + coff + (size_t)row * 1024 + col)       = make_float2(d0, d1);
                *(float2*)(Cf + coff + (size_t)(row + 8) * 1024 + col) = make_float2(d2, d3);
            }
        }
}

// ---------------- fused scores-MMA + thresholded softmax + head mean --------
// R16 structure: CTA = (b, 16 q-rows), 512 thr / 16 warps, two chunk groups
// with named barriers + per-group kp double buffer; writer-side masking;
// integer radix select with redux.sync. NEW: row-max via redux.sync.max.u32
// (monotone float map) kills the last 5-deep shfl chain; 1/16 head-mean
// folded into inv.
#define SCW 1036
#define F_QP 0                       // 2 groups x 4KB
#define F_KP 8192                    // 2 groups x 2 bufs x 32KB
#define F_SC (8192 + 131072)
#define F_KM (F_SC + 16 * SCW * 4)
#define FUSED_SMEM (F_KM + 1024)

__global__ __launch_bounds__(512, 1)
void attn_fused(const __nv_bfloat16* __restrict__ qphi, const __nv_bfloat16* __restrict__ qplo,
                const __nv_bfloat16* __restrict__ kphi, const __nv_bfloat16* __restrict__ kplo,
                const int* __restrict__ kmask, float* __restrict__ attn_out,
                __nv_bfloat16* __restrict__ ahi, __nv_bfloat16* __restrict__ alo) {
    extern __shared__ char smem[];
    const uint32_t sb = smem_u32(smem);
    const int b = blockIdx.y, r0 = blockIdx.x * 16;
    const int tid = threadIdx.x, warp = tid >> 5, lane = tid & 31;
    const int g = warp >> 3, gw = warp & 7, gtid = tid & 255;
    float* sc = (float*)(smem + F_SC);
    unsigned char* km = (unsigned char*)(smem + F_KM);

    const uint32_t myqp = sb + F_QP + g * 4096;
    const uint32_t kp0  = sb + F_KP + g * 65536;          // buffer 0
    const uint32_t kp1  = kp0 + 32768;                    // buffer 1

    for (int i = tid; i < 1024; i += 512)
        km[i] = (kmask[b * 1024 + i] > 0) ? 1 : 0;

    float acc[32];
#pragma unroll
    for (int t2 = 0; t2 < 32; ++t2) acc[t2] = 0.f;

    const int qmat = gtid >> 7, qrow = (gtid >> 3) & 15, qlc = gtid & 7;
    const int lrow = gtid >> 3, lc = gtid & 7;

    auto stage_qp = [&](int h) {
        const __nv_bfloat16* qsrc = (qmat ? qplo : qphi)
            + (size_t)(b * 1024 + r0 + qrow) * 1024 + h * 64 + qlc * 8;
        CP_ASYNC16(myqp + qmat * 2048 + qrow * 128 + ((qlc ^ (qrow & 7)) << 4), qsrc);
    };
    auto stage_chunk = [&](int h, int c, uint32_t buf) {
#pragma unroll
        for (int mat = 0; mat < 2; ++mat) {
            const __nv_bfloat16* base = mat ? kplo : kphi;
#pragma unroll
            for (int i = 0; i < 4; ++i) {
                int row = lrow + i * 32;
                const __nv_bfloat16* src = base
                    + (size_t)(b * 1024 + c * 128 + row) * 1024 + h * 64 + lc * 8;
                CP_ASYNC16(buf + mat * 16384 + row * 128 + ((lc ^ (row & 7)) << 4), src);
            }
        }
    };

    stage_qp(0);
    stage_chunk(0, g, kp0);
    CP_COMMIT();
    __syncthreads();               // km visible to both groups before scatter

    for (int h = 0; h < 16; ++h) {
        uint32_t ah[4][4], al[4][4];
        for (int ci = 0; ci < 4; ++ci) {
            const int c = g + 2 * ci;                   // this group's chunk
            const uint32_t nbuf = ((ci + 1) & 1) ? kp1 : kp0;
            if (ci < 3) {
                stage_chunk(h, c + 2, nbuf);
                CP_COMMIT();
            } else if (h < 15) {
                stage_qp(h + 1);
                stage_chunk(h + 1, g, nbuf);
                CP_COMMIT();
            }
            if (h == 15 && ci == 3) CP_WAIT0(); else CP_WAIT1();
            BARG(g + 1);                                // chunk c resident for group
            if (ci == 0) {
#pragma unroll
                for (int ks = 0; ks < 4; ++ks) {
                    ldmA(ah[ks], myqp,        0, 2 * ks, lane);
                    ldmA(al[ks], myqp + 2048, 0, 2 * ks, lane);
                }
            }
            const uint32_t cbuf = (ci & 1) ? kp1 : kp0;
            float c0a[4] = {0.f,0.f,0.f,0.f}, c0b[4] = {0.f,0.f,0.f,0.f};
            float c1a[4] = {0.f,0.f,0.f,0.f}, c1b[4] = {0.f,0.f,0.f,0.f};
#pragma unroll
            for (int ks = 0; ks < 4; ++ks) {
                uint32_t bh[4], bl[4];
                ldmB(bh, cbuf,         gw * 16, 2 * ks, lane);
                ldmB(bl, cbuf + 16384, gw * 16, 2 * ks, lane);
                mma16816(c0a, ah[ks], bh);
                mma16816(c0b, al[ks], bh);
                mma16816(c0b, ah[ks], bl);
                mma16816(c1a, ah[ks], bh + 2);
                mma16816(c1b, al[ks], bh + 2);
                mma16816(c1b, ah[ks], bl + 2);
            }
            {   // scatter this chunk's 16x16 score tile, mask applied here
                int gr = lane >> 2, tig = lane & 3;
                int colb = c * 128 + gw * 16 + 2 * tig;
                float k0f = km[colb]     ? 0.f : -FLT_MAX;
                float k1f = km[colb + 1] ? 0.f : -FLT_MAX;
                float k8f = km[colb + 8] ? 0.f : -FLT_MAX;
                float k9f = km[colb + 9] ? 0.f : -FLT_MAX;
                *(float2*)&sc[gr * SCW + colb] =
                    make_float2(k0f + (c0a[0]+c0b[0]), k1f + (c0a[1]+c0b[1]));
                *(float2*)&sc[(gr + 8) * SCW + colb] =
                    make_float2(k0f + (c0a[2]+c0b[2]), k1f + (c0a[3]+c0b[3]));
                *(float2*)&sc[gr * SCW + colb + 8] =
                    make_float2(k8f + (c1a[0]+c1b[0]), k9f + (c1a[1]+c1b[1]));
                *(float2*)&sc[(gr + 8) * SCW + colb + 8] =
                    make_float2(k8f + (c1a[2]+c1b[2]), k9f + (c1a[3]+c1b[3]));
            }
            BARG(g + 1);                                // group done reading cbuf
        }
        __syncthreads();                                // sc complete from both groups

        // ---- select: one row per warp (row = warp); sc already masked
        {
            const int row = warp;
            float pv[32];
            float m = -FLT_MAX;
#pragma unroll
            for (int c = 0; c < 8; ++c) {
                int j = c * 128 + lane * 4;
                float4 v = *(const float4*)&sc[row * SCW + j];
                pv[c*4+0] = v.x; pv[c*4+1] = v.y; pv[c*4+2] = v.z; pv[c*4+3] = v.w;
                m = fmaxf(m, fmaxf(fmaxf(v.x, v.y), fmaxf(v.z, v.w)));
            }
            m = warp_fmax(m);      // redux.max via monotone map (no shfl chain)

            // quantize p = exp(x - m) in [0,1] to u = rint(p * 2^19)
            uint32_t u[32];
            uint32_t l0 = 0, l1 = 0, l2 = 0, l3 = 0;
#pragma unroll
            for (int t2 = 0; t2 < 32; t2 += 4) {
                u[t2+0] = __float2uint_rn(__expf(pv[t2+0] - m) * 524288.f); l0 += u[t2+0];
                u[t2+1] = __float2uint_rn(__expf(pv[t2+1] - m) * 524288.f); l1 += u[t2+1];
                u[t2+2] = __float2uint_rn(__expf(pv[t2+2] - m) * 524288.f); l2 += u[t2+2];
                u[t2+3] = __float2uint_rn(__expf(pv[t2+3] - m) * 524288.f); l3 += u[t2+3];
            }
            const uint32_t Sigma = redux_add((l0 + l1) + (l2 + l3));   // Sigma <= 2^24

            // integer radix select: U = first value where inclusive cumsum
            // reaches T = Sigma/10 (criterion 10*S < Sigma, exact; 10S < 2^28).
            // Invariant: G = sum(u < U) < T. 20 rounds (u <= 2^19) -> exact.
            uint32_t U = 0, G = 0;
            for (int bit = 19; bit >= 0; --bit) {
                const uint32_t cand = U + (1u << bit);
                uint32_t s0 = 0, s1 = 0, s2 = 0, s3 = 0;
#pragma unroll
                for (int t2 = 0; t2 < 32; t2 += 4) {
                    uadd_lt(s0, u[t2+0], cand);
                    uadd_lt(s1, u[t2+1], cand);
                    uadd_lt(s2, u[t2+2], cand);
                    uadd_lt(s3, u[t2+3], cand);
                }
                const uint32_t S = redux_add((s0 + s1) + (s2 + s3));
                if (S * 10u < Sigma) { U = cand; G = S; }
            }

            // kept mass K = Sigma - G (exact int); 1/16 head-mean folded in.
            const float Zf = (float)Sigma * (1.f / 524288.f);
            const float Kf = (float)(Sigma - G) * (1.f / 524288.f);
            const float inv = (0.0625f / 524288.f) / (Kf + 1e-7f * Zf);
#pragma unroll
            for (int t2 = 0; t2 < 32; ++t2)
                pfma_ge_u(acc[t2], u[t2], inv, U);
        }
        __syncthreads();                    // select reads done before next head
    }

    // ---- epilogue: head-mean row (row = warp) -> attn fp32 + bf16 hi/lo
    {
        const int row = r0 + warp;
        size_t base = ((size_t)(b * 1024 + row)) << 10;
#pragma unroll
        for (int c = 0; c < 8; ++c) {
            int j = c * 128 + lane * 4;
            float4 v = make_float4(acc[c*4+0], acc[c*4+1], acc[c*4+2], acc[c*4+3]);
            *(float4*)(attn_out + base + j) = v;
            __nv_bfloat162 h0, h1, l0, l1;
            h0.x = __float2bfloat16(v.x); h0.y = __float2bfloat16(v.y);
            h1.x = __float2bfloat16(v.z); h1.y = __float2bfloat16(v.w);
            l0.x = __float2bfloat16(v.x - __bfloat162float(h0.x));
            l0.y = __float2bfloat16(v.y - __bfloat162float(h0.y));
            l1.x = __float2bfloat16(v.z - __bfloat162float(h1.x));
            l1.y = __float2bfloat16(v.w - __bfloat162float(h1.y));
            *(__nv_bfloat162*)(ahi + base + j)     = h0;
            *(__nv_bfloat162*)(ahi + base + j + 2) = h1;
            *(__nv_bfloat162*)(alo + base + j)     = l0;
            *(__nv_bfloat162*)(alo + base + j + 2) = l1;
        }
    }
}

// ---------------- Launch ------------------------------------------------------
extern "C" void kernel_launch(void* const* d_in, const int* in_sizes, int n_in,
                              void* d_out, int out_size) {
    const float* q     = (const float*)d_in[0];
    const float* k     = (const float*)d_in[1];
    const float* v     = (const float*)d_in[2];
    const float* Wq    = (const float*)d_in[3];
    const float* Wk    = (const float*)d_in[4];
    const int*   kmask = (const int*)d_in[5];
    float*       out   = (float*)d_out;

    __nv_bfloat16 *inhi, *inlo, *whi, *wlo, *pphi, *pplo, *athi, *atlo, *vthi, *vtlo;
    cudaGetSymbolAddress((void**)&inhi, g_inhi);
    cudaGetSymbolAddress((void**)&inlo, g_inlo);
    cudaGetSymbolAddress((void**)&whi,  g_whi);
    cudaGetSymbolAddress((void**)&wlo,  g_wlo);
    cudaGetSymbolAddress((void**)&pphi, g_pphi);
    cudaGetSymbolAddress((void**)&pplo, g_pplo);
    cudaGetSymbolAddress((void**)&athi, g_athi);
    cudaGetSymbolAddress((void**)&atlo, g_atlo);
    cudaGetSymbolAddress((void**)&vthi, g_vthi);
    cudaGetSymbolAddress((void**)&vtlo, g_vtlo);

    cudaFuncSetAttribute(mma_gemm<0>, cudaFuncAttributeMaxDynamicSharedMemorySize, GEMM_SMEM);
    cudaFuncSetAttribute(mma_gemm<1>, cudaFuncAttributeMaxDynamicSharedMemorySize, GEMM_SMEM);
    cudaFuncSetAttribute(attn_fused,  cudaFuncAttributeMaxDynamicSharedMemorySize, FUSED_SMEM);

    const size_t M4 = 4u << 20, M1 = 1u << 20;

    // 1: all four splits + v transpose in one launch
    prep_kernel<<<14336, 256>>>(q, k, Wq, Wk, v, inhi, inlo, whi, wlo, vthi, vtlo);

    // 2: projections z=0 -> qp, z=1 -> kp, bf16 hi/lo out
    mma_gemm<1><<<dim3(8, 32, 2), 256, GEMM_SMEM>>>(
        inhi, inlo, whi, wlo, nullptr, pphi, pplo, M4, M1, M4, 1024);

    // 3: fused scores + thresholded softmax + head mean
    attn_fused<<<dim3(64, 4), 512, FUSED_SMEM>>>(
        pphi, pplo, pphi + M4, pplo + M4, kmask, out + M4, athi, atlo);

    // 4 (profiled launch): out = attn @ vT^T (z = batch)
    mma_gemm<0><<<dim3(8, 8, 4), 256, GEMM_SMEM>>>(
        athi, atlo, vthi, vtlo, out, nullptr, nullptr, M1, M1, M1, 1024);
}